// round 14
// baseline (speedup 1.0000x reference)
#include <cuda_runtime.h>
#include <cuda_bf16.h>
#include <math.h>

#define NMAX 100000
#define EMAX 1600000
#define IN_F 64
#define HID_F 16
#define OUT_F 40
#define CAP 64
#define GRID_P 740          // 148 SMs x 5 blocks (guaranteed co-resident via launch_bounds)
#define THREADS_P 256
#define QUADS_P (GRID_P * (THREADS_P / 4))

// ---------------- scratch (device globals: allocation-free, zero-initialized) --------
// Row NMAX of every gatherable buffer is a permanent zero row (never written):
// out-of-range record slots are clamped to it inside the gather loop.
// g_deg/g_cnt self-clean in the persistent kernel -> every execution starts clean.
__device__ float g_deg[NMAX];                   // out-degree accumulator
__device__ int   g_cnt[NMAX];                   // in-degree / fill cursor (by col)
__device__ int2  g_meta[NMAX];                  // {cnt, dis_bits}
__device__ __align__(16) int g_edge[NMAX * CAP + 32];  // src indices, fixed-cap segments
__device__ float g_Y[(NMAX + 1) * 48];          // U0=Y0-Y2+b1 | U1=Y1 | rawY2
__device__ __align__(64) float g_u2s[(NMAX + 1) * 16];  // U2s = dis*rawY2 (packed)
__device__ float g_h[(NMAX + 1) * 32];          // h | hs=dis*h
__device__ float g_accA[(NMAX + 1) * 16];       // As = dis*A
__device__ float g_accC[(NMAX + 1) * 32];       // C | Cs=dis*C
__device__ float g_accD[NMAX * 16];             // D

// grid barrier state (generation counters are monotonic across launches/replays)
__device__ int g_bar[8];
__device__ volatile int g_gen[8];

__device__ __forceinline__ void red_add_f32(float* addr, float v) {
    asm volatile("red.global.add.f32 [%0], %1;" :: "l"(addr), "f"(v) : "memory");
}

__device__ __forceinline__ void grid_barrier(int i) {
    __syncthreads();
    if (threadIdx.x == 0) {
        __threadfence();
        int my = g_gen[i];                    // read before own arrival -> always pre-bump
        int old = atomicAdd(&g_bar[i], 1);
        if (old == GRID_P - 1) {
            g_bar[i] = 0;                     // reset for next launch/replay
            __threadfence();
            g_gen[i] = my + 1;                // release
        } else {
            while (g_gen[i] == my) __nanosleep(64);
        }
    }
    __syncthreads();
}

// ---------------- fill_direct: one edge pass does hist(row) + bucket-place(col) -----
__global__ void fill_kernel(const int* __restrict__ row, const int* __restrict__ col, int E) {
    int t = blockIdx.x * blockDim.x + threadIdx.x;
    int e0 = t * 8;
    if (e0 >= E) return;
    if (e0 + 8 <= E) {
        int4 r0 = *(const int4*)(row + e0);
        int4 r1 = *(const int4*)(row + e0 + 4);
        int4 c0 = *(const int4*)(col + e0);
        int4 c1 = *(const int4*)(col + e0 + 4);
        red_add_f32(&g_deg[r0.x], 1.0f); red_add_f32(&g_deg[r0.y], 1.0f);
        red_add_f32(&g_deg[r0.z], 1.0f); red_add_f32(&g_deg[r0.w], 1.0f);
        red_add_f32(&g_deg[r1.x], 1.0f); red_add_f32(&g_deg[r1.y], 1.0f);
        red_add_f32(&g_deg[r1.z], 1.0f); red_add_f32(&g_deg[r1.w], 1.0f);
        int p;
        p = atomicAdd(&g_cnt[c0.x], 1); if (p < CAP) g_edge[c0.x * CAP + p] = r0.x;
        p = atomicAdd(&g_cnt[c0.y], 1); if (p < CAP) g_edge[c0.y * CAP + p] = r0.y;
        p = atomicAdd(&g_cnt[c0.z], 1); if (p < CAP) g_edge[c0.z * CAP + p] = r0.z;
        p = atomicAdd(&g_cnt[c0.w], 1); if (p < CAP) g_edge[c0.w * CAP + p] = r0.w;
        p = atomicAdd(&g_cnt[c1.x], 1); if (p < CAP) g_edge[c1.x * CAP + p] = r1.x;
        p = atomicAdd(&g_cnt[c1.y], 1); if (p < CAP) g_edge[c1.y * CAP + p] = r1.y;
        p = atomicAdd(&g_cnt[c1.z], 1); if (p < CAP) g_edge[c1.z * CAP + p] = r1.z;
        p = atomicAdd(&g_cnt[c1.w], 1); if (p < CAP) g_edge[c1.w * CAP + p] = r1.w;
    } else {
        for (int e = e0; e < E; e++) {
            int r = row[e], c = col[e];
            red_add_f32(&g_deg[r], 1.0f);
            int p = atomicAdd(&g_cnt[c], 1);
            if (p < CAP) g_edge[c * CAP + p] = r;
        }
    }
}

// ------------- GEMM1: per node writes U0 = Y0-Y2+b1 | U1 = Y1 | rawY2 ---------
// (independent of CSR build — runs concurrently on side stream)
__global__ void gemm1_kernel(const float* __restrict__ x, const float* __restrict__ W1,
                             const float* __restrict__ b1, int N) {
    __shared__ float sW[IN_F * 48];
    __shared__ float sb1[16];
    for (int t = threadIdx.x; t < 3 * IN_F * HID_F; t += blockDim.x) {
        int k = t / (IN_F * HID_F);
        int r = t % (IN_F * HID_F);
        int i = r / HID_F, j = r % HID_F;
        sW[i * 48 + k * 16 + j] = W1[t];
    }
    if (threadIdx.x < 16) sb1[threadIdx.x] = b1[threadIdx.x];
    __syncthreads();
    int warp = threadIdx.x >> 5, lane = threadIdx.x & 31;
    int nodeBase = (blockIdx.x * 8 + warp) * 16;
    for (int nn = 0; nn < 16; nn++) {
        int node = nodeBase + nn;
        if (node >= N) return;
        const float4* xr = (const float4*)(x + (size_t)node * IN_F);
        float a0 = 0.f, a1 = 0.f;
#pragma unroll
        for (int i4 = 0; i4 < 16; i4++) {
            float4 xv = xr[i4];
            int i = i4 * 4;
            a0 += xv.x * sW[(i    ) * 48 + lane] + xv.y * sW[(i + 1) * 48 + lane]
                + xv.z * sW[(i + 2) * 48 + lane] + xv.w * sW[(i + 3) * 48 + lane];
            if (lane < 16) {
                a1 += xv.x * sW[(i    ) * 48 + 32 + lane] + xv.y * sW[(i + 1) * 48 + 32 + lane]
                    + xv.z * sW[(i + 2) * 48 + 32 + lane] + xv.w * sW[(i + 3) * 48 + 32 + lane];
            }
        }
        if (lane < 16) {
            g_Y[(size_t)node * 48 + lane]      = a0 - a1 + sb1[lane];  // U0
            g_Y[(size_t)node * 48 + 32 + lane] = a1;                   // rawY2
        } else {
            g_Y[(size_t)node * 48 + lane]      = a0;                   // U1
        }
    }
}

// ------------- gather body (round-9 winner): 4 threads/node, 8 records/iter ---------
template <int SSTR, int SOFF, int EPI>
__device__ __forceinline__ void gather_node(const float* __restrict__ src,
                                            float* __restrict__ dst, int n, int ch) {
    int2 m = g_meta[n];
    const int4* ep4 = (const int4*)(g_edge + (size_t)n * CAP);
    int cnt = m.x;
    float dis = __int_as_float(m.y);
    float ax = 0.f, ay = 0.f, az = 0.f, aw = 0.f;
    for (int i = 0; i < cnt; i += 8) {
        int4 ra = ep4[(i >> 2)];
        int4 rb = ep4[(i >> 2) + 1];
        int i0 = (i + 0 < cnt) ? ra.x : NMAX;
        int i1 = (i + 1 < cnt) ? ra.y : NMAX;
        int i2 = (i + 2 < cnt) ? ra.z : NMAX;
        int i3 = (i + 3 < cnt) ? ra.w : NMAX;
        int i4 = (i + 4 < cnt) ? rb.x : NMAX;
        int i5 = (i + 5 < cnt) ? rb.y : NMAX;
        int i6 = (i + 6 < cnt) ? rb.z : NMAX;
        int i7 = (i + 7 < cnt) ? rb.w : NMAX;
        float4 v0 = *(const float4*)(src + (size_t)i0 * SSTR + SOFF + ch * 4);
        float4 v1 = *(const float4*)(src + (size_t)i1 * SSTR + SOFF + ch * 4);
        float4 v2 = *(const float4*)(src + (size_t)i2 * SSTR + SOFF + ch * 4);
        float4 v3 = *(const float4*)(src + (size_t)i3 * SSTR + SOFF + ch * 4);
        float4 v4 = *(const float4*)(src + (size_t)i4 * SSTR + SOFF + ch * 4);
        float4 v5 = *(const float4*)(src + (size_t)i5 * SSTR + SOFF + ch * 4);
        float4 v6 = *(const float4*)(src + (size_t)i6 * SSTR + SOFF + ch * 4);
        float4 v7 = *(const float4*)(src + (size_t)i7 * SSTR + SOFF + ch * 4);
        ax += ((v0.x + v1.x) + (v2.x + v3.x)) + ((v4.x + v5.x) + (v6.x + v7.x));
        ay += ((v0.y + v1.y) + (v2.y + v3.y)) + ((v4.y + v5.y) + (v6.y + v7.y));
        az += ((v0.z + v1.z) + (v2.z + v3.z)) + ((v4.z + v5.z) + (v6.z + v7.z));
        aw += ((v0.w + v1.w) + (v2.w + v3.w)) + ((v4.w + v5.w) + (v6.w + v7.w));
    }
    if (EPI == 1) {
        float4 u1 = *(const float4*)(g_Y + (size_t)n * 48 + 16 + ch * 4);
        float4 r = make_float4(dis * (u1.x - 2.f * dis * ax), dis * (u1.y - 2.f * dis * ay),
                               dis * (u1.z - 2.f * dis * az), dis * (u1.w - 2.f * dis * aw));
        *(float4*)(dst + (size_t)n * 16 + ch * 4) = r;
    } else if (EPI == 2) {
        float4 u0 = *(const float4*)(g_Y + (size_t)n * 48 + ch * 4);
        float4 h = make_float4(fmaxf(u0.x - dis * ax, 0.f), fmaxf(u0.y - dis * ay, 0.f),
                               fmaxf(u0.z - dis * az, 0.f), fmaxf(u0.w - dis * aw, 0.f));
        *(float4*)(dst + (size_t)n * 32 + ch * 4) = h;
        float4 hs = make_float4(dis * h.x, dis * h.y, dis * h.z, dis * h.w);
        *(float4*)(dst + (size_t)n * 32 + 16 + ch * 4) = hs;
    } else if (EPI == 3) {
        float4 c = make_float4(-dis * ax, -dis * ay, -dis * az, -dis * aw);
        *(float4*)(dst + (size_t)n * 32 + ch * 4) = c;
        float4 cs = make_float4(dis * c.x, dis * c.y, dis * c.z, dis * c.w);
        *(float4*)(dst + (size_t)n * 32 + 16 + ch * 4) = cs;
    } else {
        float4 r = make_float4(-dis * ax, -dis * ay, -dis * az, -dis * aw);
        *(float4*)(dst + (size_t)n * 16 + ch * 4) = r;
    }
}

// ------------- persistent kernel: postfill + 4 Lhat passes, grid barriers between ---
__global__ void __launch_bounds__(THREADS_P, 5)
persistent_kernel(int N) {
    int tid = blockIdx.x * blockDim.x + threadIdx.x;
    int q = tid >> 2;          // quad id
    int ch = tid & 3;

    // pass 0: postfill (dis + meta + packed U2s + counter self-clean)
    for (int n = q; n < N; n += QUADS_P) {
        int cnt = g_cnt[n];
        if (cnt > CAP) cnt = CAP;
        float d = g_deg[n];
        float dis = (d > 0.f) ? rsqrtf(d) : 0.f;
        if (ch == 0) {
            g_meta[n] = make_int2(cnt, __float_as_int(dis));
            g_cnt[n] = 0;
            g_deg[n] = 0.f;
        }
        float4 v = *(const float4*)(g_Y + (size_t)n * 48 + 32 + ch * 4);
        v.x *= dis; v.y *= dis; v.z *= dis; v.w *= dis;
        *(float4*)(g_u2s + (size_t)n * 16 + ch * 4) = v;
    }
    grid_barrier(0);

    // pass 1: As = dis*(U1 - 2*dis*Lhat_t(U2s))
    for (int n = q; n < N; n += QUADS_P)
        gather_node<16, 0, 1>(g_u2s, g_accA, n, ch);
    grid_barrier(1);

    // pass 2: h = relu(U0 - dis*t(As)); hs = dis*h
    for (int n = q; n < N; n += QUADS_P)
        gather_node<16, 0, 2>(g_accA, g_h, n, ch);
    grid_barrier(2);

    // pass 3: C = -dis*t(hs); Cs = dis*C
    for (int n = q; n < N; n += QUADS_P)
        gather_node<32, 16, 3>(g_h, g_accC, n, ch);
    grid_barrier(3);

    // pass 4: D = -dis*t(Cs)
    for (int n = q; n < N; n += QUADS_P)
        gather_node<32, 16, 4>(g_accC, g_accD, n, ch);
}

// ------------- final fused GEMM + bias + log_softmax -------------
__global__ void final_kernel(const float* __restrict__ W2, const float* __restrict__ b2,
                             float* __restrict__ out, int N) {
    __shared__ float sW[48 * 40];
    __shared__ float sb[40];
    for (int t = threadIdx.x; t < HID_F * OUT_F; t += blockDim.x) {
        sW[t]           = W2[t] - W2[2 * 640 + t];   // W2[0]-W2[2]
        sW[16 * 40 + t] = W2[640 + t];               // W2[1]
        sW[32 * 40 + t] = 2.f * W2[2 * 640 + t];     // 2*W2[2]
    }
    if (threadIdx.x < OUT_F) sb[threadIdx.x] = b2[threadIdx.x];
    __syncthreads();

    int n = blockIdx.x * blockDim.x + threadIdx.x;
    if (n >= N) return;

    float4 acc[10];
#pragma unroll
    for (int jj = 0; jj < 10; jj++)
        acc[jj] = make_float4(sb[jj*4], sb[jj*4+1], sb[jj*4+2], sb[jj*4+3]);

    const float4* sW4 = (const float4*)sW;
    const float* srcs[3] = { g_h    + (size_t)n * 32,
                             g_accC + (size_t)n * 32,
                             g_accD + (size_t)n * 16 };
#pragma unroll
    for (int b = 0; b < 3; b++) {
        float4 f4[4];
        const float4* s = (const float4*)srcs[b];
#pragma unroll
        for (int q = 0; q < 4; q++) f4[q] = s[q];
        const float* f = (const float*)f4;
#pragma unroll
        for (int i = 0; i < 16; i++) {
            float fv = f[i];
            const float4* wrow = sW4 + (b * 16 + i) * 10;
#pragma unroll
            for (int jj = 0; jj < 10; jj++) {
                float4 w = wrow[jj];
                acc[jj].x += fv * w.x; acc[jj].y += fv * w.y;
                acc[jj].z += fv * w.z; acc[jj].w += fv * w.w;
            }
        }
    }

    float* a = (float*)acc;
    float m = a[0];
#pragma unroll
    for (int j = 1; j < 40; j++) m = fmaxf(m, a[j]);
    float sum = 0.f;
#pragma unroll
    for (int j = 0; j < 40; j++) sum += __expf(a[j] - m);
    float ls = m + __logf(sum);
    float* o = out + (size_t)n * 40;
#pragma unroll
    for (int jj = 0; jj < 10; jj++) {
        float4 v = acc[jj];
        v.x -= ls; v.y -= ls; v.z -= ls; v.w -= ls;
        ((float4*)o)[jj] = v;
    }
}

// ---------------- host launcher ----------------
extern "C" void kernel_launch(void* const* d_in, const int* in_sizes, int n_in,
                              void* d_out, int out_size) {
    const float* x  = (const float*)d_in[0];
    const int*   ei = (const int*)d_in[1];
    const float* W1 = (const float*)d_in[2];
    const float* b1 = (const float*)d_in[3];
    const float* W2 = (const float*)d_in[4];
    const float* b2 = (const float*)d_in[5];
    float* out = (float*)d_out;

    int N = in_sizes[0] / IN_F;
    int E = in_sizes[1] / 2;
    if (N > NMAX) N = NMAX;
    if (E > EMAX) E = EMAX;
    const int* row = ei;
    const int* col = ei + E;

    // one-time side stream + events (host resources only; no device memory)
    static cudaStream_t s1 = nullptr;
    static cudaEvent_t evRoot = nullptr, evSide = nullptr;
    if (!s1) {
        cudaStreamCreateWithFlags(&s1, cudaStreamNonBlocking);
        cudaEventCreateWithFlags(&evRoot, cudaEventDisableTiming);
        cudaEventCreateWithFlags(&evSide, cudaEventDisableTiming);
    }

    const int T = 256;
    auto blocks = [](long n, int t) { return (int)((n + t - 1) / t); };

    // fork: gemm1 on side stream (independent of CSR build)
    cudaEventRecord(evRoot, 0);
    cudaStreamWaitEvent(s1, evRoot, 0);
    gemm1_kernel<<<blocks((long)N, 128), 256, 0, s1>>>(x, W1, b1, N);
    cudaEventRecord(evSide, s1);

    // main stream: direct-placement CSR build (one edge pass; counters pre-zeroed)
    fill_kernel<<<blocks(((long)E + 7) / 8, T), T>>>(row, col, E);

    // join gemm1, then the persistent fused kernel (postfill + 4 Lhat passes)
    cudaStreamWaitEvent(0, evSide, 0);
    persistent_kernel<<<GRID_P, THREADS_P>>>(N);

    final_kernel<<<blocks((long)N, T), T>>>(W2, b2, out, N);
}

// round 15
// speedup vs baseline: 1.0823x; 1.0823x over previous
#include <cuda_runtime.h>
#include <cuda_bf16.h>
#include <math.h>

#define NMAX 100000
#define EMAX 1600000
#define IN_F 64
#define HID_F 16
#define OUT_F 40
#define CAP 64

// ---------------- scratch (device globals: allocation-free, zero-initialized) --------
// Row NMAX of every gatherable buffer is a permanent zero row (never written):
// out-of-range record slots are clamped to it inside the gather loop (L1-hot).
// g_deg/g_cnt are reset to zero by postfill after use -> every execution starts clean.
__device__ float g_deg[NMAX];                   // out-degree accumulator
__device__ int   g_cnt[NMAX];                   // in-degree / fill cursor (by col)
__device__ int2  g_meta[NMAX];                  // {cnt, dis_bits}
__device__ __align__(16) int g_edge[NMAX * CAP];  // src indices, fixed-cap segments
__device__ float g_Y[(NMAX + 1) * 48];          // U0=Y0-Y2+b1 | U1=Y1 | rawY2 -> U2s
__device__ float g_h[(NMAX + 1) * 32];          // h | hs=dis*h
__device__ float g_accA[(NMAX + 1) * 16];       // As = dis*A
__device__ float g_accC[(NMAX + 1) * 32];       // C | Cs=dis*C
__device__ float g_accD[NMAX * 16];             // D

__device__ __forceinline__ void red_add_f32(float* addr, float v) {
    asm volatile("red.global.add.f32 [%0], %1;" :: "l"(addr), "f"(v) : "memory");
}

// ---------------- fill_direct: one edge pass does hist(row) + bucket-place(col) -----
__global__ void fill_kernel(const int* __restrict__ row, const int* __restrict__ col, int E) {
    int base = blockIdx.x * 2048 + threadIdx.x;
#pragma unroll
    for (int k = 0; k < 8; k++) {
        int e = base + k * 256;
        if (e < E) {
            int r = row[e], c = col[e];
            red_add_f32(&g_deg[r], 1.0f);
            int pos = atomicAdd(&g_cnt[c], 1);
            if (pos < CAP) g_edge[c * CAP + pos] = r;
        }
    }
}

// ------------- GEMM1: per node writes U0 = Y0-Y2+b1 | U1 = Y1 | rawY2 ---------
// (independent of CSR build — runs concurrently on side stream)
__global__ void gemm1_kernel(const float* __restrict__ x, const float* __restrict__ W1,
                             const float* __restrict__ b1, int N) {
    __shared__ float sW[IN_F * 48];
    __shared__ float sb1[16];
    for (int t = threadIdx.x; t < 3 * IN_F * HID_F; t += blockDim.x) {
        int k = t / (IN_F * HID_F);
        int r = t % (IN_F * HID_F);
        int i = r / HID_F, j = r % HID_F;
        sW[i * 48 + k * 16 + j] = W1[t];
    }
    if (threadIdx.x < 16) sb1[threadIdx.x] = b1[threadIdx.x];
    __syncthreads();
    int warp = threadIdx.x >> 5, lane = threadIdx.x & 31;
    int nodeBase = (blockIdx.x * 8 + warp) * 16;
    for (int nn = 0; nn < 16; nn++) {
        int node = nodeBase + nn;
        if (node >= N) return;
        const float4* xr = (const float4*)(x + (size_t)node * IN_F);
        float a0 = 0.f, a1 = 0.f;
#pragma unroll
        for (int i4 = 0; i4 < 16; i4++) {
            float4 xv = xr[i4];
            int i = i4 * 4;
            a0 += xv.x * sW[(i    ) * 48 + lane] + xv.y * sW[(i + 1) * 48 + lane]
                + xv.z * sW[(i + 2) * 48 + lane] + xv.w * sW[(i + 3) * 48 + lane];
            if (lane < 16) {
                a1 += xv.x * sW[(i    ) * 48 + 32 + lane] + xv.y * sW[(i + 1) * 48 + 32 + lane]
                    + xv.z * sW[(i + 2) * 48 + 32 + lane] + xv.w * sW[(i + 3) * 48 + 32 + lane];
            }
        }
        if (lane < 16) {
            g_Y[(size_t)node * 48 + lane]      = a0 - a1 + sb1[lane];  // U0
            g_Y[(size_t)node * 48 + 32 + lane] = a1;                   // rawY2
        } else {
            g_Y[(size_t)node * 48 + lane]      = a0;                   // U1
        }
    }
}

// ------------- postfill: dis + meta + U2s scaling + counter self-clean --------------
__global__ void postfill_kernel(int N) {
    int tid = blockIdx.x * blockDim.x + threadIdx.x;
    int n = tid >> 2;
    if (n >= N) return;
    int ch = tid & 3;
    int cnt = g_cnt[n];
    if (cnt > CAP) cnt = CAP;
    float d = g_deg[n];
    float dis = (d > 0.f) ? rsqrtf(d) : 0.f;
    if (ch == 0) {
        g_meta[n] = make_int2(cnt, __float_as_int(dis));
        g_cnt[n] = 0;      // self-clean for next execution
        g_deg[n] = 0.f;
    }
    // U2s = dis * rawY2 (gemm1 joined before this kernel)
    float4* p = (float4*)(g_Y + (size_t)n * 48 + 32 + ch * 4);
    float4 v = *p;
    v.x *= dis; v.y *= dis; v.z *= dis; v.w *= dis;
    *p = v;
}

// ------------- unweighted CSR gather, F=16, 4 threads/node, 8 records/iter ----------
// t = sum_{src in nbr} src_feat  (out-of-range slots clamped to permanent zero row)
// EPI 1: As = dis*(U1 - 2*dis*t)             -> dst stride 16
// EPI 2: h = relu(U0 - dis*t); hs = dis*h    -> dst stride 32 (h|hs)
// EPI 3: C = -dis*t; Cs = dis*C              -> dst stride 32 (C|Cs)
// EPI 4: D = -dis*t                          -> dst stride 16
template <int SSTR, int SOFF, int EPI>
__global__ void gather16(const float* __restrict__ src, float* __restrict__ dst, int N) {
    int tid = blockIdx.x * blockDim.x + threadIdx.x;
    int n = tid >> 2;
    if (n >= N) return;
    int ch = tid & 3;
    int2 m = g_meta[n];
    const int4* ep4 = (const int4*)(g_edge + (size_t)n * CAP);
    int cnt = m.x;
    float dis = __int_as_float(m.y);
    float ax = 0.f, ay = 0.f, az = 0.f, aw = 0.f;
    for (int i = 0; i < cnt; i += 8) {
        int4 ra = ep4[(i >> 2)];
        int4 rb = ep4[(i >> 2) + 1];
        int i0 = (i + 0 < cnt) ? ra.x : NMAX;
        int i1 = (i + 1 < cnt) ? ra.y : NMAX;
        int i2 = (i + 2 < cnt) ? ra.z : NMAX;
        int i3 = (i + 3 < cnt) ? ra.w : NMAX;
        int i4 = (i + 4 < cnt) ? rb.x : NMAX;
        int i5 = (i + 5 < cnt) ? rb.y : NMAX;
        int i6 = (i + 6 < cnt) ? rb.z : NMAX;
        int i7 = (i + 7 < cnt) ? rb.w : NMAX;
        float4 v0 = *(const float4*)(src + (size_t)i0 * SSTR + SOFF + ch * 4);
        float4 v1 = *(const float4*)(src + (size_t)i1 * SSTR + SOFF + ch * 4);
        float4 v2 = *(const float4*)(src + (size_t)i2 * SSTR + SOFF + ch * 4);
        float4 v3 = *(const float4*)(src + (size_t)i3 * SSTR + SOFF + ch * 4);
        float4 v4 = *(const float4*)(src + (size_t)i4 * SSTR + SOFF + ch * 4);
        float4 v5 = *(const float4*)(src + (size_t)i5 * SSTR + SOFF + ch * 4);
        float4 v6 = *(const float4*)(src + (size_t)i6 * SSTR + SOFF + ch * 4);
        float4 v7 = *(const float4*)(src + (size_t)i7 * SSTR + SOFF + ch * 4);
        ax += ((v0.x + v1.x) + (v2.x + v3.x)) + ((v4.x + v5.x) + (v6.x + v7.x));
        ay += ((v0.y + v1.y) + (v2.y + v3.y)) + ((v4.y + v5.y) + (v6.y + v7.y));
        az += ((v0.z + v1.z) + (v2.z + v3.z)) + ((v4.z + v5.z) + (v6.z + v7.z));
        aw += ((v0.w + v1.w) + (v2.w + v3.w)) + ((v4.w + v5.w) + (v6.w + v7.w));
    }
    if (EPI == 1) {
        float4 u1 = *(const float4*)(g_Y + (size_t)n * 48 + 16 + ch * 4);
        float4 r = make_float4(dis * (u1.x - 2.f * dis * ax), dis * (u1.y - 2.f * dis * ay),
                               dis * (u1.z - 2.f * dis * az), dis * (u1.w - 2.f * dis * aw));
        *(float4*)(dst + (size_t)n * 16 + ch * 4) = r;
    } else if (EPI == 2) {
        float4 u0 = *(const float4*)(g_Y + (size_t)n * 48 + ch * 4);
        float4 h = make_float4(fmaxf(u0.x - dis * ax, 0.f), fmaxf(u0.y - dis * ay, 0.f),
                               fmaxf(u0.z - dis * az, 0.f), fmaxf(u0.w - dis * aw, 0.f));
        *(float4*)(dst + (size_t)n * 32 + ch * 4) = h;
        float4 hs = make_float4(dis * h.x, dis * h.y, dis * h.z, dis * h.w);
        *(float4*)(dst + (size_t)n * 32 + 16 + ch * 4) = hs;
    } else if (EPI == 3) {
        float4 c = make_float4(-dis * ax, -dis * ay, -dis * az, -dis * aw);
        *(float4*)(dst + (size_t)n * 32 + ch * 4) = c;
        float4 cs = make_float4(dis * c.x, dis * c.y, dis * c.z, dis * c.w);
        *(float4*)(dst + (size_t)n * 32 + 16 + ch * 4) = cs;
    } else {
        float4 r = make_float4(-dis * ax, -dis * ay, -dis * az, -dis * aw);
        *(float4*)(dst + (size_t)n * 16 + ch * 4) = r;
    }
}

// ------------- final fused GEMM + bias + log_softmax, 2 threads/node ----------------
// Thread ch in {0,1} computes logits [20ch, 20ch+20); pair combines max/sum via shfl.
__global__ void final_kernel(const float* __restrict__ W2, const float* __restrict__ b2,
                             float* __restrict__ out, int N) {
    __shared__ float sW[48 * 40];
    __shared__ float sb[40];
    for (int t = threadIdx.x; t < HID_F * OUT_F; t += blockDim.x) {
        sW[t]           = W2[t] - W2[2 * 640 + t];   // W2[0]-W2[2]
        sW[16 * 40 + t] = W2[640 + t];               // W2[1]
        sW[32 * 40 + t] = 2.f * W2[2 * 640 + t];     // 2*W2[2]
    }
    if (threadIdx.x < OUT_F) sb[threadIdx.x] = b2[threadIdx.x];
    __syncthreads();

    int tid = blockIdx.x * blockDim.x + threadIdx.x;
    int n = tid >> 1;
    bool valid = (n < N);
    if (n >= N) n = N - 1;          // clamp: all lanes participate in shuffles
    int ch = tid & 1;               // output half: columns [20ch, 20ch+20)

    float4 acc[5];
#pragma unroll
    for (int jj = 0; jj < 5; jj++) {
        int j = ch * 20 + jj * 4;
        acc[jj] = make_float4(sb[j], sb[j + 1], sb[j + 2], sb[j + 3]);
    }

    const float4* sW4 = (const float4*)sW;   // [48 rows][10 float4]
    const float* srcs[3] = { g_h    + (size_t)n * 32,
                             g_accC + (size_t)n * 32,
                             g_accD + (size_t)n * 16 };
#pragma unroll
    for (int b = 0; b < 3; b++) {
        float4 f4[4];
        const float4* s = (const float4*)srcs[b];
#pragma unroll
        for (int q = 0; q < 4; q++) f4[q] = s[q];
        const float* f = (const float*)f4;
#pragma unroll
        for (int i = 0; i < 16; i++) {
            float fv = f[i];
            const float4* wrow = sW4 + (b * 16 + i) * 10 + ch * 5;
#pragma unroll
            for (int jj = 0; jj < 5; jj++) {
                float4 w = wrow[jj];
                acc[jj].x += fv * w.x; acc[jj].y += fv * w.y;
                acc[jj].z += fv * w.z; acc[jj].w += fv * w.w;
            }
        }
    }

    // log_softmax across the pair
    float* a = (float*)acc;
    float m = a[0];
#pragma unroll
    for (int j = 1; j < 20; j++) m = fmaxf(m, a[j]);
    m = fmaxf(m, __shfl_xor_sync(0xffffffffu, m, 1));
    float sum = 0.f;
#pragma unroll
    for (int j = 0; j < 20; j++) sum += __expf(a[j] - m);
    sum += __shfl_xor_sync(0xffffffffu, sum, 1);
    float ls = m + __logf(sum);
    if (!valid) return;
    float* o = out + (size_t)n * 40 + ch * 20;
#pragma unroll
    for (int jj = 0; jj < 5; jj++) {
        float4 v = acc[jj];
        v.x -= ls; v.y -= ls; v.z -= ls; v.w -= ls;
        ((float4*)o)[jj] = v;
    }
}

// ---------------- host launcher ----------------
static float* sym_addr(const void* sym) {
    void* p = nullptr;
    cudaGetSymbolAddress(&p, sym);
    return (float*)p;
}

extern "C" void kernel_launch(void* const* d_in, const int* in_sizes, int n_in,
                              void* d_out, int out_size) {
    const float* x  = (const float*)d_in[0];
    const int*   ei = (const int*)d_in[1];
    const float* W1 = (const float*)d_in[2];
    const float* b1 = (const float*)d_in[3];
    const float* W2 = (const float*)d_in[4];
    const float* b2 = (const float*)d_in[5];
    float* out = (float*)d_out;

    int N = in_sizes[0] / IN_F;
    int E = in_sizes[1] / 2;
    if (N > NMAX) N = NMAX;
    if (E > EMAX) E = EMAX;
    const int* row = ei;
    const int* col = ei + E;

    float* p_Y  = sym_addr(g_Y);
    float* p_h  = sym_addr(g_h);
    float* p_A  = sym_addr(g_accA);
    float* p_C  = sym_addr(g_accC);
    float* p_D  = sym_addr(g_accD);

    // one-time side stream + events (host resources only; no device memory)
    static cudaStream_t s1 = nullptr;
    static cudaEvent_t evRoot = nullptr, evSide = nullptr;
    if (!s1) {
        cudaStreamCreateWithFlags(&s1, cudaStreamNonBlocking);
        cudaEventCreateWithFlags(&evRoot, cudaEventDisableTiming);
        cudaEventCreateWithFlags(&evSide, cudaEventDisableTiming);
    }

    const int T = 256;
    auto blocks = [](long n, int t) { return (int)((n + t - 1) / t); };

    // fork: gemm1 on side stream (independent of CSR build)
    cudaEventRecord(evRoot, 0);
    cudaStreamWaitEvent(s1, evRoot, 0);
    gemm1_kernel<<<blocks((long)N, 128), 256, 0, s1>>>(x, W1, b1, N);
    cudaEventRecord(evSide, s1);

    // main stream: direct-placement CSR build (one edge pass; counters pre-zeroed)
    fill_kernel<<<blocks(E, 2048), T>>>(row, col, E);

    // join gemm1, then postfill (dis + meta + U2s scale + self-clean)
    cudaStreamWaitEvent(0, evSide, 0);
    postfill_kernel<<<blocks((long)N * 4, T), T>>>(N);

    // layer 1 gathers
    gather16<48, 32, 1><<<blocks((long)N * 4, T), T>>>(p_Y, p_A, N);   // As
    gather16<16, 0, 2><<<blocks((long)N * 4, T), T>>>(p_A, p_h, N);    // h | hs

    // layer 2
    gather16<32, 16, 3><<<blocks((long)N * 4, T), T>>>(p_h, p_C, N);   // C | Cs
    gather16<32, 16, 4><<<blocks((long)N * 4, T), T>>>(p_C, p_D, N);   // D
    final_kernel<<<blocks((long)N * 2, T), T>>>(W2, b2, out, N);
}